// round 15
// baseline (speedup 1.0000x reference)
#include <cuda_runtime.h>
#include <cuda_bf16.h>
#include <cstdint>

#define N_NODES 163842
#define N_EDGES 983040
#define SCAN_B  1024
#define SCAN_NB ((N_NODES + SCAN_B - 1) / SCAN_B)   // 161

// ---------------- scratch (device globals; no allocation allowed) ----------------
__device__ float d_h0[(size_t)N_NODES * 64];
__device__ float d_h1[(size_t)N_NODES * 64];
__device__ __align__(16) __nv_bfloat16 d_Bg[3][2][64 * 264]; // per-layer hi/lo B [COUT][BS]
__device__ float4 d_g4[3][N_EDGES];              // per-layer gaussians + src (CSR order)
__device__ int   d_src[N_EDGES];
__device__ int   d_dst[N_EDGES];
__device__ int   d_cnt[N_NODES];
__device__ int   d_incl[N_NODES];
__device__ int   d_rowptr[N_NODES + 1];
__device__ int   d_cursor[N_NODES];
__device__ int   d_bsum[SCAN_NB];
__device__ int   d_is64;

// ---------------- PTX helpers (generic features only: ldmatrix + mma.sync) --------
__device__ __forceinline__ uint32_t smem_u32(const void* p) {
    uint32_t a;
    asm("{ .reg .u64 t; cvta.to.shared.u64 t, %1; cvt.u32.u64 %0, t; }" : "=r"(a) : "l"(p));
    return a;
}
#define LDM4(r, addr)                                                           \
    asm volatile("ldmatrix.sync.aligned.m8n8.x4.shared.b16 {%0,%1,%2,%3}, [%4];"\
        : "=r"((r)[0]), "=r"((r)[1]), "=r"((r)[2]), "=r"((r)[3]) : "r"(addr))
#define MMA_BF16(c, a, b)                                                       \
    asm volatile("mma.sync.aligned.m16n8k16.row.col.f32.bf16.bf16.f32 "         \
        "{%0,%1,%2,%3}, {%4,%5,%6,%7}, {%8,%9}, {%0,%1,%2,%3};"                 \
        : "+f"((c)[0]), "+f"((c)[1]), "+f"((c)[2]), "+f"((c)[3])                \
        : "r"((a)[0]), "r"((a)[1]), "r"((a)[2]), "r"((a)[3]),                   \
          "r"((b)[0]), "r"((b)[1]))

__device__ __forceinline__ void bf_split(float v, __nv_bfloat16& h, __nv_bfloat16& l) {
    h = __float2bfloat16(v);
    l = __float2bfloat16(v - __bfloat162float(h));
}

// ---------------- zero counters + edge dtype detect (merged) ----------------
__global__ void zero_cnt(const unsigned* ei) {
    int i = blockIdx.x * blockDim.x + threadIdx.x;
    if (i < N_NODES) d_cnt[i] = 0;
    if (blockIdx.x == 0 && threadIdx.x == 0) {
        int ok = 1;
        for (int j = 1; j < 64; j += 2)
            if (ei[j] != 0u) ok = 0;
        d_is64 = ok;
    }
}

__global__ void convert_hist(const void* eiv) {
    int e = blockIdx.x * blockDim.x + threadIdx.x;
    if (e >= N_EDGES) return;
    int s, d;
    if (d_is64) {
        const long long* ei = (const long long*)eiv;
        s = (int)ei[e]; d = (int)ei[N_EDGES + e];
    } else {
        const int* ei = (const int*)eiv;
        s = ei[e]; d = ei[N_EDGES + e];
    }
    d_src[e] = s;
    d_dst[e] = d;
    atomicAdd(&d_cnt[d], 1);
}

// ---------------- CSR build ----------------
__global__ void scan1() {
    __shared__ int s[2][SCAN_B];
    int t = threadIdx.x;
    int i = blockIdx.x * SCAN_B + t;
    int v = (i < N_NODES) ? d_cnt[i] : 0;
    s[0][t] = v;
    int cur = 0;
    for (int off = 1; off < SCAN_B; off <<= 1) {
        __syncthreads();
        int nv = s[cur][t] + (t >= off ? s[cur][t - off] : 0);
        s[cur ^ 1][t] = nv;
        cur ^= 1;
    }
    __syncthreads();
    if (i < N_NODES) d_incl[i] = s[cur][t];
    if (t == SCAN_B - 1) d_bsum[blockIdx.x] = s[cur][t];
}

__global__ void scan2() {
    __shared__ int s[2][256];
    int t = threadIdx.x;
    int v = (t < SCAN_NB) ? d_bsum[t] : 0;
    s[0][t] = v;
    int cur = 0;
    for (int off = 1; off < 256; off <<= 1) {
        __syncthreads();
        int nv = s[cur][t] + (t >= off ? s[cur][t - off] : 0);
        s[cur ^ 1][t] = nv;
        cur ^= 1;
    }
    __syncthreads();
    if (t < SCAN_NB) d_bsum[t] = s[cur][t] - v;        // exclusive
    if (t == 255) d_rowptr[N_NODES] = s[cur][t];
}

__global__ void scan3() {
    int i = blockIdx.x * blockDim.x + threadIdx.x;
    if (i >= N_NODES) return;
    int excl = d_incl[i] - d_cnt[i] + d_bsum[i / SCAN_B];
    d_rowptr[i] = excl;
    d_cursor[i] = excl;
}

// ---------------- fill CSR: gaussians for all 3 layers + src packed in .w ---------
__global__ void fill_gauss(const float* __restrict__ ea,
                           const float* __restrict__ mu0, const float* __restrict__ sg0,
                           const float* __restrict__ mu1, const float* __restrict__ sg1,
                           const float* __restrict__ mu2, const float* __restrict__ sg2) {
    int e = blockIdx.x * blockDim.x + threadIdx.x;
    if (e >= N_EDGES) return;
    int s = d_src[e];
    int p = atomicAdd(&d_cursor[d_dst[e]], 1);
    float2 pc = ((const float2*)ea)[e];
    const float* mus[3] = {mu0, mu1, mu2};
    const float* sgs[3] = {sg0, sg1, sg2};
#pragma unroll
    for (int l = 0; l < 3; l++) {
        float g[3];
#pragma unroll
        for (int k = 0; k < 3; k++) {
            float dd0 = pc.x - mus[l][2 * k];
            float dd1 = pc.y - mus[l][2 * k + 1];
            float s0 = sgs[l][2 * k], s1 = sgs[l][2 * k + 1];
            float q = dd0 * dd0 / (1e-15f + s0 * s0) + dd1 * dd1 / (1e-15f + s1 * s1);
            g[k] = __expf(-0.5f * q);
        }
        d_g4[l][p] = make_float4(g[0], g[1], g[2], __int_as_float(s));
    }
}

// ---------------- pack B (hi/lo bf16): B[n][k] = W[k][n], zero-pad k>=4Cin --------
template <int CIN, int COUT, int K4P>
__global__ void pack_bg(const float* __restrict__ g,
                        const float* __restrict__ root,
                        __nv_bfloat16* __restrict__ bh,
                        __nv_bfloat16* __restrict__ bl) {
    constexpr int K3 = 3 * CIN, K4 = 4 * CIN, BS = K4P + 8;
    int i = blockIdx.x * blockDim.x + threadIdx.x;
    if (i >= COUT * K4P) return;
    int n = i / K4P, k = i - n * K4P;
    float v = 0.f;
    if (k < K3) {
        int kk = k / CIN, c = k - kk * CIN;
        v = g[c * (3 * COUT) + kk * COUT + n];
    } else if (k < K4) {
        v = root[(k - K3) * COUT + n];
    }
    __nv_bfloat16 hi, lo;
    bf_split(v, hi, lo);
    bh[n * BS + k] = hi;
    bl[n * BS + k] = lo;
}

// ---------------- fused layer: pipelined gather -> bf16x3 HMMA -> epilogue --------
// BN=64 nodes/block, 256 threads (8 warps = 4 m-tiles x 2 n-groups).
template <int CIN, int COUT, int K4P, bool FINAL>
__global__ void __launch_bounds__(256)
layer_mma(const float* __restrict__ x,
          const __nv_bfloat16* __restrict__ bghi,
          const __nv_bfloat16* __restrict__ bglo,
          const float4* __restrict__ g4,
          const float* __restrict__ bias,
          const float* __restrict__ fcw,
          const float* __restrict__ fcb,
          float* __restrict__ out) {
    constexpr int K4 = 4 * CIN;
    constexpr int AS = K4P + 8;                    // bf16 row stride (A smem)
    constexpr int BS = K4P + 8;                    // bf16 row stride (B global)
    constexpr int TPW = COUT / 16;                 // n-tiles per warp
    constexpr int HSS = COUT + 2;
    constexpr int CPL = (CIN + 31) / 32;

    extern __shared__ __align__(16) char smem[];
    __nv_bfloat16* ahi = (__nv_bfloat16*)smem;
    __nv_bfloat16* alo = ahi + 64 * AS;
    float* hs = (float*)smem;                      // FINAL overlay (after sync)

    const int tid = threadIdx.x;
    const int warp = tid >> 5, lane = tid & 31;
    const int n0b = blockIdx.x * 64;

    // ---- gather: 8 warps x 8 nodes, 2-stage software pipeline ----
    const __nv_bfloat16 bz = __float2bfloat16(0.f);
    for (int j = warp * 8; j < warp * 8 + 8; j++) {
        int n = n0b + j;
        __nv_bfloat16* rh = ahi + j * AS;
        __nv_bfloat16* rl = alo + j * AS;
        if (n >= N_NODES) {
            for (int c = lane; c < K4P; c += 32) { rh[c] = bz; rl[c] = bz; }
            continue;
        }
        int beg = d_rowptr[n], end = d_rowptr[n + 1];
        int deg = end - beg;
        float a0[CPL], a1[CPL], a2[CPL];
#pragma unroll
        for (int r = 0; r < CPL; r++) { a0[r] = 0.f; a1[r] = 0.f; a2[r] = 0.f; }

        float4 ga = make_float4(0.f, 0.f, 0.f, 0.f);
        float4 gb = ga, gc = ga;
        float xa[CPL], xb[CPL];
#pragma unroll
        for (int r = 0; r < CPL; r++) { xa[r] = 0.f; xb[r] = 0.f; }

        if (deg > 0) ga = g4[beg];
        if (deg > 1) gb = g4[beg + 1];
        if (deg > 0) {
            int s = __float_as_int(ga.w);
#pragma unroll
            for (int r = 0; r < CPL; r++) {
                int c = lane + 32 * r;
                xa[r] = (c < CIN) ? x[(size_t)s * CIN + c] : 0.f;
            }
        }
        for (int i = 0; i < deg; i++) {
            if (i + 2 < deg) gc = g4[beg + i + 2];           // prefetch g4, dist 2
            if (i + 1 < deg) {                               // prefetch x row, dist 1
                int s = __float_as_int(gb.w);
#pragma unroll
                for (int r = 0; r < CPL; r++) {
                    int c = lane + 32 * r;
                    xb[r] = (c < CIN) ? x[(size_t)s * CIN + c] : 0.f;
                }
            }
#pragma unroll
            for (int r = 0; r < CPL; r++) {
                a0[r] += ga.x * xa[r];
                a1[r] += ga.y * xa[r];
                a2[r] += ga.z * xa[r];
            }
            ga = gb; gb = gc;
#pragma unroll
            for (int r = 0; r < CPL; r++) xa[r] = xb[r];
        }

        float inv = 1.f / fmaxf((float)deg, 1.f);
#pragma unroll
        for (int r = 0; r < CPL; r++) {
            int c = lane + 32 * r;
            if (c < CIN) {
                __nv_bfloat16 hi, lo;
                bf_split(a0[r] * inv, hi, lo);
                rh[c] = hi;            rl[c] = lo;
                bf_split(a1[r] * inv, hi, lo);
                rh[CIN + c] = hi;      rl[CIN + c] = lo;
                bf_split(a2[r] * inv, hi, lo);
                rh[2 * CIN + c] = hi;  rl[2 * CIN + c] = lo;
                bf_split(x[(size_t)n * CIN + c], hi, lo);
                rh[3 * CIN + c] = hi;  rl[3 * CIN + c] = lo;
            }
        }
        for (int c = K4 + lane; c < K4P; c += 32) { rh[c] = bz; rl[c] = bz; }  // zero pad
    }
    __syncthreads();

    // ---- bf16x3 MMA: D = Ahi@Bhi + Ahi@Blo + Alo@Bhi (B fragments from global) ---
    const int m0 = (warp & 3) * 16;
    const int ngrp = warp >> 2;
    float acc[TPW][4];
#pragma unroll
    for (int t = 0; t < TPW; t++)
#pragma unroll
        for (int v = 0; v < 4; v++) acc[t][v] = 0.f;

    const uint32_t a_hi = smem_u32(ahi), a_lo = smem_u32(alo);
    const int arow = m0 + (lane & 15);
    const int acol = (lane >> 4) * 8;
    const int kp = (lane & 3) * 2;
    const __nv_bfloat16* bhrow[TPW];
    const __nv_bfloat16* blrow[TPW];
#pragma unroll
    for (int t = 0; t < TPW; t++) {
        int nn = (ngrp * TPW + t) * 8 + (lane >> 2);
        bhrow[t] = bghi + nn * BS + kp;
        blrow[t] = bglo + nn * BS + kp;
    }
#pragma unroll
    for (int ks = 0; ks < K4P; ks += 16) {
        uint32_t ah[4], al[4];
        uint32_t aoff = (uint32_t)((arow * AS + ks + acol) * 2);
        LDM4(ah, a_hi + aoff);
        LDM4(al, a_lo + aoff);
#pragma unroll
        for (int t = 0; t < TPW; t++) {
            uint32_t bh[2], bl[2];
            bh[0] = *(const uint32_t*)(bhrow[t] + ks);
            bh[1] = *(const uint32_t*)(bhrow[t] + ks + 8);
            bl[0] = *(const uint32_t*)(blrow[t] + ks);
            bl[1] = *(const uint32_t*)(blrow[t] + ks + 8);
            MMA_BF16(acc[t], ah, bh);
            MMA_BF16(acc[t], ah, bl);
            MMA_BF16(acc[t], al, bh);
        }
    }

    if (!FINAL) {
        // ---- direct fragment store: bias + relu ----
        int r0 = m0 + (lane >> 2);
        int n1 = n0b + r0, n2 = n1 + 8;
#pragma unroll
        for (int t = 0; t < TPW; t++) {
            int nc = (ngrp * TPW + t) * 8 + kp;
            float b0 = bias[nc], b1 = bias[nc + 1];
            if (n1 < N_NODES) {
                float2 v;
                v.x = fmaxf(acc[t][0] + b0, 0.f);
                v.y = fmaxf(acc[t][1] + b1, 0.f);
                *(float2*)&out[(size_t)n1 * COUT + nc] = v;
            }
            if (n2 < N_NODES) {
                float2 v;
                v.x = fmaxf(acc[t][2] + b0, 0.f);
                v.y = fmaxf(acc[t][3] + b1, 0.f);
                *(float2*)&out[(size_t)n2 * COUT + nc] = v;
            }
        }
    } else {
        // ---- dump to hs, then per-node FC + log_softmax ----
        __syncthreads();                           // A smem dead -> overlay hs
        {
            int r0 = m0 + (lane >> 2);
#pragma unroll
            for (int t = 0; t < TPW; t++) {
                int nc = (ngrp * TPW + t) * 8 + kp;
                hs[r0 * HSS + nc]           = acc[t][0];
                hs[r0 * HSS + nc + 1]       = acc[t][1];
                hs[(r0 + 8) * HSS + nc]     = acc[t][2];
                hs[(r0 + 8) * HSS + nc + 1] = acc[t][3];
            }
        }
        __syncthreads();
        if (tid < 64) {
            int n = n0b + tid;
            if (n < N_NODES) {
                const float* row = hs + tid * HSS;
                float p0 = fcb[0], p1 = fcb[1];
#pragma unroll
                for (int c = 0; c < COUT; c++) {
                    float hv = fmaxf(row[c] + bias[c], 0.f);
                    p0 += hv * fcw[2 * c];
                    p1 += hv * fcw[2 * c + 1];
                }
                float mx = fmaxf(p0, p1);
                float lse = mx + logf(expf(p0 - mx) + expf(p1 - mx));
                out[(size_t)n * 2]     = p0 - lse;
                out[(size_t)n * 2 + 1] = p1 - lse;
            }
        }
    }
}

// ---------------- launch ----------------------------------------------------------
extern "C" void kernel_launch(void* const* d_in, const int* in_sizes, int n_in,
                              void* d_out, int out_size) {
    const float* x   = (const float*)d_in[0];
    const void*  ei  = d_in[1];
    const float* ea  = (const float*)d_in[2];
    const float* g[3]  = {(const float*)d_in[3],  (const float*)d_in[8],  (const float*)d_in[13]};
    const float* mu[3] = {(const float*)d_in[4],  (const float*)d_in[9],  (const float*)d_in[14]};
    const float* sg[3] = {(const float*)d_in[5],  (const float*)d_in[10], (const float*)d_in[15]};
    const float* rt[3] = {(const float*)d_in[6],  (const float*)d_in[11], (const float*)d_in[16]};
    const float* bi[3] = {(const float*)d_in[7],  (const float*)d_in[12], (const float*)d_in[17]};
    const float* fcw = (const float*)d_in[18];
    const float* fcb = (const float*)d_in[19];
    float* out = (float*)d_out;

    float *h0, *h1;
    float4* g4;
    __nv_bfloat16* Bg;
    cudaGetSymbolAddress((void**)&h0, d_h0);
    cudaGetSymbolAddress((void**)&h1, d_h1);
    cudaGetSymbolAddress((void**)&g4, d_g4);
    cudaGetSymbolAddress((void**)&Bg, d_Bg);
    __nv_bfloat16* B0h = Bg;                 __nv_bfloat16* B0l = Bg + 64 * 264;
    __nv_bfloat16* B1h = Bg + 2 * 64 * 264;  __nv_bfloat16* B1l = Bg + 3 * 64 * 264;
    __nv_bfloat16* B2h = Bg + 4 * 64 * 264;  __nv_bfloat16* B2l = Bg + 5 * 64 * 264;

    // smem: A hi/lo only: 64 * (K4P+8) * 2 * 2 bytes
    const int SM0 = 64 * 104 * 4;   // 26,624
    const int SM1 = 64 * 136 * 4;   // 34,816
    const int SM2 = 64 * 264 * 4;   // 67,584
    cudaFuncSetAttribute(layer_mma<22, 32, 96,  false>,
                         cudaFuncAttributeMaxDynamicSharedMemorySize, SM0);
    cudaFuncSetAttribute(layer_mma<32, 64, 128, false>,
                         cudaFuncAttributeMaxDynamicSharedMemorySize, SM1);
    cudaFuncSetAttribute(layer_mma<64, 64, 256, true>,
                         cudaFuncAttributeMaxDynamicSharedMemorySize, SM2);

    const int EB = (N_EDGES + 255) / 256;
    const int NB = (N_NODES + 255) / 256;
    const int GB = (N_NODES + 63) / 64;            // 2561 blocks

    // ---- CSR build + weight packing (shared prep) ----
    zero_cnt<<<NB, 256>>>((const unsigned*)ei);
    convert_hist<<<EB, 256>>>(ei);
    scan1<<<SCAN_NB, SCAN_B>>>();
    scan2<<<1, 256>>>();
    scan3<<<NB, 256>>>();
    fill_gauss<<<EB, 256>>>(ea, mu[0], sg[0], mu[1], sg[1], mu[2], sg[2]);
    pack_bg<22, 32, 96 ><<<(32 * 96  + 255) / 256, 256>>>(g[0], rt[0], B0h, B0l);
    pack_bg<32, 64, 128><<<(64 * 128 + 255) / 256, 256>>>(g[1], rt[1], B1h, B1l);
    pack_bg<64, 64, 256><<<(64 * 256 + 255) / 256, 256>>>(g[2], rt[2], B2h, B2l);

    // ---- fused layers (bf16x3 HMMA, pipelined gather) ----
    layer_mma<22, 32, 96,  false><<<GB, 256, SM0>>>(x,  B0h, B0l, g4,                       bi[0], fcw, fcb, h0);
    layer_mma<32, 64, 128, false><<<GB, 256, SM1>>>(h0, B1h, B1l, g4 + N_EDGES,             bi[1], fcw, fcb, h1);
    layer_mma<64, 64, 256, true ><<<GB, 256, SM2>>>(h1, B2h, B2l, g4 + 2 * (size_t)N_EDGES, bi[2], fcw, fcb, out);
}

// round 17
// speedup vs baseline: 1.1421x; 1.1421x over previous
#include <cuda_runtime.h>
#include <cuda_bf16.h>
#include <cstdint>

#define N_NODES 163842
#define N_EDGES 983040
#define SCAN_B  1024
#define SCAN_NB ((N_NODES + SCAN_B - 1) / SCAN_B)   // 161

// ---------------- scratch (device globals; no allocation allowed) ----------------
__device__ float d_h0[(size_t)N_NODES * 64];
__device__ float d_h1[(size_t)N_NODES * 64];
__device__ __align__(16) __nv_bfloat16 d_Bg[3][2][64 * 264]; // per-layer hi/lo B [COUT][BS]
__device__ float4 d_g4[3][N_EDGES];              // per-layer gaussians + src (CSR order)
__device__ int   d_src[N_EDGES];
__device__ int   d_dst[N_EDGES];
__device__ int   d_cnt[N_NODES];
__device__ int   d_incl[N_NODES];
__device__ int   d_rowptr[N_NODES + 1];
__device__ int   d_cursor[N_NODES];
__device__ int   d_bsum[SCAN_NB];
__device__ int   d_is64;

// ---------------- PTX helpers (generic features only: ldmatrix + mma.sync) --------
__device__ __forceinline__ uint32_t smem_u32(const void* p) {
    uint32_t a;
    asm("{ .reg .u64 t; cvta.to.shared.u64 t, %1; cvt.u32.u64 %0, t; }" : "=r"(a) : "l"(p));
    return a;
}
#define LDM4(r, addr)                                                           \
    asm volatile("ldmatrix.sync.aligned.m8n8.x4.shared.b16 {%0,%1,%2,%3}, [%4];"\
        : "=r"((r)[0]), "=r"((r)[1]), "=r"((r)[2]), "=r"((r)[3]) : "r"(addr))
#define MMA_BF16(c, a, b)                                                       \
    asm volatile("mma.sync.aligned.m16n8k16.row.col.f32.bf16.bf16.f32 "         \
        "{%0,%1,%2,%3}, {%4,%5,%6,%7}, {%8,%9}, {%0,%1,%2,%3};"                 \
        : "+f"((c)[0]), "+f"((c)[1]), "+f"((c)[2]), "+f"((c)[3])                \
        : "r"((a)[0]), "r"((a)[1]), "r"((a)[2]), "r"((a)[3]),                   \
          "r"((b)[0]), "r"((b)[1]))

__device__ __forceinline__ void bf_split(float v, __nv_bfloat16& h, __nv_bfloat16& l) {
    h = __float2bfloat16(v);
    l = __float2bfloat16(v - __bfloat162float(h));
}

// ---------------- zero counters + edge dtype detect (merged) ----------------
__global__ void zero_cnt(const unsigned* ei) {
    int i = blockIdx.x * blockDim.x + threadIdx.x;
    if (i < N_NODES) d_cnt[i] = 0;
    if (blockIdx.x == 0 && threadIdx.x == 0) {
        int ok = 1;
        for (int j = 1; j < 64; j += 2)
            if (ei[j] != 0u) ok = 0;
        d_is64 = ok;
    }
}

__global__ void convert_hist(const void* eiv) {
    int e = blockIdx.x * blockDim.x + threadIdx.x;
    if (e >= N_EDGES) return;
    int s, d;
    if (d_is64) {
        const long long* ei = (const long long*)eiv;
        s = (int)ei[e]; d = (int)ei[N_EDGES + e];
    } else {
        const int* ei = (const int*)eiv;
        s = ei[e]; d = ei[N_EDGES + e];
    }
    d_src[e] = s;
    d_dst[e] = d;
    atomicAdd(&d_cnt[d], 1);
}

// ---------------- CSR build ----------------
__global__ void scan1() {
    __shared__ int s[2][SCAN_B];
    int t = threadIdx.x;
    int i = blockIdx.x * SCAN_B + t;
    int v = (i < N_NODES) ? d_cnt[i] : 0;
    s[0][t] = v;
    int cur = 0;
    for (int off = 1; off < SCAN_B; off <<= 1) {
        __syncthreads();
        int nv = s[cur][t] + (t >= off ? s[cur][t - off] : 0);
        s[cur ^ 1][t] = nv;
        cur ^= 1;
    }
    __syncthreads();
    if (i < N_NODES) d_incl[i] = s[cur][t];
    if (t == SCAN_B - 1) d_bsum[blockIdx.x] = s[cur][t];
}

__global__ void scan2() {
    __shared__ int s[2][256];
    int t = threadIdx.x;
    int v = (t < SCAN_NB) ? d_bsum[t] : 0;
    s[0][t] = v;
    int cur = 0;
    for (int off = 1; off < 256; off <<= 1) {
        __syncthreads();
        int nv = s[cur][t] + (t >= off ? s[cur][t - off] : 0);
        s[cur ^ 1][t] = nv;
        cur ^= 1;
    }
    __syncthreads();
    if (t < SCAN_NB) d_bsum[t] = s[cur][t] - v;        // exclusive
    if (t == 255) d_rowptr[N_NODES] = s[cur][t];
}

__global__ void scan3() {
    int i = blockIdx.x * blockDim.x + threadIdx.x;
    if (i >= N_NODES) return;
    int excl = d_incl[i] - d_cnt[i] + d_bsum[i / SCAN_B];
    d_rowptr[i] = excl;
    d_cursor[i] = excl;
}

// ---------------- fill CSR: gaussians for all 3 layers + src packed in .w ---------
__global__ void fill_gauss(const float* __restrict__ ea,
                           const float* __restrict__ mu0, const float* __restrict__ sg0,
                           const float* __restrict__ mu1, const float* __restrict__ sg1,
                           const float* __restrict__ mu2, const float* __restrict__ sg2) {
    int e = blockIdx.x * blockDim.x + threadIdx.x;
    if (e >= N_EDGES) return;
    int s = d_src[e];
    int p = atomicAdd(&d_cursor[d_dst[e]], 1);
    float2 pc = ((const float2*)ea)[e];
    const float* mus[3] = {mu0, mu1, mu2};
    const float* sgs[3] = {sg0, sg1, sg2};
#pragma unroll
    for (int l = 0; l < 3; l++) {
        float g[3];
#pragma unroll
        for (int k = 0; k < 3; k++) {
            float dd0 = pc.x - mus[l][2 * k];
            float dd1 = pc.y - mus[l][2 * k + 1];
            float s0 = sgs[l][2 * k], s1 = sgs[l][2 * k + 1];
            float q = dd0 * dd0 / (1e-15f + s0 * s0) + dd1 * dd1 / (1e-15f + s1 * s1);
            g[k] = __expf(-0.5f * q);
        }
        d_g4[l][p] = make_float4(g[0], g[1], g[2], __int_as_float(s));
    }
}

// ---------------- pack B (hi/lo bf16): B[n][k] = W[k][n], zero-pad k>=4Cin --------
template <int CIN, int COUT, int K4P>
__global__ void pack_bg(const float* __restrict__ g,
                        const float* __restrict__ root,
                        __nv_bfloat16* __restrict__ bh,
                        __nv_bfloat16* __restrict__ bl) {
    constexpr int K3 = 3 * CIN, K4 = 4 * CIN, BS = K4P + 8;
    int i = blockIdx.x * blockDim.x + threadIdx.x;
    if (i >= COUT * K4P) return;
    int n = i / K4P, k = i - n * K4P;
    float v = 0.f;
    if (k < K3) {
        int kk = k / CIN, c = k - kk * CIN;
        v = g[c * (3 * COUT) + kk * COUT + n];
    } else if (k < K4) {
        v = root[(k - K3) * COUT + n];
    }
    __nv_bfloat16 hi, lo;
    bf_split(v, hi, lo);
    bh[n * BS + k] = hi;
    bl[n * BS + k] = lo;
}

// ---------------- fused layer: batched gather -> bf16x3 HMMA -> epilogue ----------
// BN=64 nodes/block, 256 threads (8 warps = 4 m-tiles x 2 n-groups).
template <int CIN, int COUT, int K4P, bool FINAL>
__global__ void __launch_bounds__(256)
layer_mma(const float* __restrict__ x,
          const __nv_bfloat16* __restrict__ bghi,
          const __nv_bfloat16* __restrict__ bglo,
          const float4* __restrict__ g4,
          const float* __restrict__ bias,
          const float* __restrict__ fcw,
          const float* __restrict__ fcb,
          float* __restrict__ out) {
    constexpr int K4 = 4 * CIN;
    constexpr int AS = K4P + 8;                    // bf16 row stride (A smem)
    constexpr int BS = K4P + 8;                    // bf16 row stride (B global)
    constexpr int TPW = COUT / 16;                 // n-tiles per warp
    constexpr int HSS = COUT + 2;
    constexpr int CPL = (CIN + 31) / 32;

    extern __shared__ __align__(16) char smem[];
    __nv_bfloat16* ahi = (__nv_bfloat16*)smem;
    __nv_bfloat16* alo = ahi + 64 * AS;
    float* hs = (float*)smem;                      // FINAL overlay (after sync)

    const int tid = threadIdx.x;
    const int warp = tid >> 5, lane = tid & 31;
    const int n0b = blockIdx.x * 64;

    // ---- gather: 8 warps x 8 nodes, branch-free unroll-by-4 batches (MLP 4) ----
    const __nv_bfloat16 bz = __float2bfloat16(0.f);
    for (int j = warp * 8; j < warp * 8 + 8; j++) {
        int n = n0b + j;
        __nv_bfloat16* rh = ahi + j * AS;
        __nv_bfloat16* rl = alo + j * AS;
        if (n >= N_NODES) {
            for (int c = lane; c < K4P; c += 32) { rh[c] = bz; rl[c] = bz; }
            continue;
        }
        int beg = d_rowptr[n], end = d_rowptr[n + 1];
        int deg = end - beg;
        float a0[CPL], a1[CPL], a2[CPL];
#pragma unroll
        for (int r = 0; r < CPL; r++) { a0[r] = 0.f; a1[r] = 0.f; a2[r] = 0.f; }

        const float4 gzero = make_float4(0.f, 0.f, 0.f, __int_as_float(0));
        for (int i = beg; i < end; i += 4) {
            // 4 independent g4 loads (oob -> zero weight, src 0)
            float4 g0 = (i     < end) ? g4[i]     : gzero;
            float4 g1 = (i + 1 < end) ? g4[i + 1] : gzero;
            float4 g2 = (i + 2 < end) ? g4[i + 2] : gzero;
            float4 g3 = (i + 3 < end) ? g4[i + 3] : gzero;
            int s0 = __float_as_int(g0.w), s1 = __float_as_int(g1.w);
            int s2 = __float_as_int(g2.w), s3 = __float_as_int(g3.w);
            // 4 independent x-row loads
            float x0[CPL], x1[CPL], x2[CPL], x3[CPL];
#pragma unroll
            for (int r = 0; r < CPL; r++) {
                int c = lane + 32 * r;
                bool ok = (c < CIN);
                x0[r] = ok ? x[(size_t)s0 * CIN + c] : 0.f;
                x1[r] = ok ? x[(size_t)s1 * CIN + c] : 0.f;
                x2[r] = ok ? x[(size_t)s2 * CIN + c] : 0.f;
                x3[r] = ok ? x[(size_t)s3 * CIN + c] : 0.f;
            }
#pragma unroll
            for (int r = 0; r < CPL; r++) {
                a0[r] += g0.x * x0[r] + g1.x * x1[r] + g2.x * x2[r] + g3.x * x3[r];
                a1[r] += g0.y * x0[r] + g1.y * x1[r] + g2.y * x2[r] + g3.y * x3[r];
                a2[r] += g0.z * x0[r] + g1.z * x1[r] + g2.z * x2[r] + g3.z * x3[r];
            }
        }

        float inv = 1.f / fmaxf((float)deg, 1.f);
#pragma unroll
        for (int r = 0; r < CPL; r++) {
            int c = lane + 32 * r;
            if (c < CIN) {
                __nv_bfloat16 hi, lo;
                bf_split(a0[r] * inv, hi, lo);
                rh[c] = hi;            rl[c] = lo;
                bf_split(a1[r] * inv, hi, lo);
                rh[CIN + c] = hi;      rl[CIN + c] = lo;
                bf_split(a2[r] * inv, hi, lo);
                rh[2 * CIN + c] = hi;  rl[2 * CIN + c] = lo;
                bf_split(x[(size_t)n * CIN + c], hi, lo);
                rh[3 * CIN + c] = hi;  rl[3 * CIN + c] = lo;
            }
        }
        for (int c = K4 + lane; c < K4P; c += 32) { rh[c] = bz; rl[c] = bz; }  // zero pad
    }
    __syncthreads();

    // ---- bf16x3 MMA: D = Ahi@Bhi + Ahi@Blo + Alo@Bhi (B fragments from global) ---
    const int m0 = (warp & 3) * 16;
    const int ngrp = warp >> 2;
    float acc[TPW][4];
#pragma unroll
    for (int t = 0; t < TPW; t++)
#pragma unroll
        for (int v = 0; v < 4; v++) acc[t][v] = 0.f;

    const uint32_t a_hi = smem_u32(ahi), a_lo = smem_u32(alo);
    const int arow = m0 + (lane & 15);
    const int acol = (lane >> 4) * 8;
    const int kp = (lane & 3) * 2;
    const __nv_bfloat16* bhrow[TPW];
    const __nv_bfloat16* blrow[TPW];
#pragma unroll
    for (int t = 0; t < TPW; t++) {
        int nn = (ngrp * TPW + t) * 8 + (lane >> 2);
        bhrow[t] = bghi + nn * BS + kp;
        blrow[t] = bglo + nn * BS + kp;
    }
#pragma unroll
    for (int ks = 0; ks < K4P; ks += 16) {
        uint32_t ah[4], al[4];
        uint32_t aoff = (uint32_t)((arow * AS + ks + acol) * 2);
        LDM4(ah, a_hi + aoff);
        LDM4(al, a_lo + aoff);
#pragma unroll
        for (int t = 0; t < TPW; t++) {
            uint32_t bh[2], bl[2];
            bh[0] = *(const uint32_t*)(bhrow[t] + ks);
            bh[1] = *(const uint32_t*)(bhrow[t] + ks + 8);
            bl[0] = *(const uint32_t*)(blrow[t] + ks);
            bl[1] = *(const uint32_t*)(blrow[t] + ks + 8);
            MMA_BF16(acc[t], ah, bh);
            MMA_BF16(acc[t], ah, bl);
            MMA_BF16(acc[t], al, bh);
        }
    }

    if (!FINAL) {
        // ---- direct fragment store: bias + relu ----
        int r0 = m0 + (lane >> 2);
        int n1 = n0b + r0, n2 = n1 + 8;
#pragma unroll
        for (int t = 0; t < TPW; t++) {
            int nc = (ngrp * TPW + t) * 8 + kp;
            float b0 = bias[nc], b1 = bias[nc + 1];
            if (n1 < N_NODES) {
                float2 v;
                v.x = fmaxf(acc[t][0] + b0, 0.f);
                v.y = fmaxf(acc[t][1] + b1, 0.f);
                *(float2*)&out[(size_t)n1 * COUT + nc] = v;
            }
            if (n2 < N_NODES) {
                float2 v;
                v.x = fmaxf(acc[t][2] + b0, 0.f);
                v.y = fmaxf(acc[t][3] + b1, 0.f);
                *(float2*)&out[(size_t)n2 * COUT + nc] = v;
            }
        }
    } else {
        // ---- dump to hs, then per-node FC + log_softmax ----
        __syncthreads();                           // A smem dead -> overlay hs
        {
            int r0 = m0 + (lane >> 2);
#pragma unroll
            for (int t = 0; t < TPW; t++) {
                int nc = (ngrp * TPW + t) * 8 + kp;
                hs[r0 * HSS + nc]           = acc[t][0];
                hs[r0 * HSS + nc + 1]       = acc[t][1];
                hs[(r0 + 8) * HSS + nc]     = acc[t][2];
                hs[(r0 + 8) * HSS + nc + 1] = acc[t][3];
            }
        }
        __syncthreads();
        if (tid < 64) {
            int n = n0b + tid;
            if (n < N_NODES) {
                const float* row = hs + tid * HSS;
                float p0 = fcb[0], p1 = fcb[1];
#pragma unroll
                for (int c = 0; c < COUT; c++) {
                    float hv = fmaxf(row[c] + bias[c], 0.f);
                    p0 += hv * fcw[2 * c];
                    p1 += hv * fcw[2 * c + 1];
                }
                float mx = fmaxf(p0, p1);
                float lse = mx + logf(expf(p0 - mx) + expf(p1 - mx));
                out[(size_t)n * 2]     = p0 - lse;
                out[(size_t)n * 2 + 1] = p1 - lse;
            }
        }
    }
}

// ---------------- launch ----------------------------------------------------------
extern "C" void kernel_launch(void* const* d_in, const int* in_sizes, int n_in,
                              void* d_out, int out_size) {
    const float* x   = (const float*)d_in[0];
    const void*  ei  = d_in[1];
    const float* ea  = (const float*)d_in[2];
    const float* g[3]  = {(const float*)d_in[3],  (const float*)d_in[8],  (const float*)d_in[13]};
    const float* mu[3] = {(const float*)d_in[4],  (const float*)d_in[9],  (const float*)d_in[14]};
    const float* sg[3] = {(const float*)d_in[5],  (const float*)d_in[10], (const float*)d_in[15]};
    const float* rt[3] = {(const float*)d_in[6],  (const float*)d_in[11], (const float*)d_in[16]};
    const float* bi[3] = {(const float*)d_in[7],  (const float*)d_in[12], (const float*)d_in[17]};
    const float* fcw = (const float*)d_in[18];
    const float* fcb = (const float*)d_in[19];
    float* out = (float*)d_out;

    float *h0, *h1;
    float4* g4;
    __nv_bfloat16* Bg;
    cudaGetSymbolAddress((void**)&h0, d_h0);
    cudaGetSymbolAddress((void**)&h1, d_h1);
    cudaGetSymbolAddress((void**)&g4, d_g4);
    cudaGetSymbolAddress((void**)&Bg, d_Bg);
    __nv_bfloat16* B0h = Bg;                 __nv_bfloat16* B0l = Bg + 64 * 264;
    __nv_bfloat16* B1h = Bg + 2 * 64 * 264;  __nv_bfloat16* B1l = Bg + 3 * 64 * 264;
    __nv_bfloat16* B2h = Bg + 4 * 64 * 264;  __nv_bfloat16* B2l = Bg + 5 * 64 * 264;

    // smem: A hi/lo only: 64 * (K4P+8) * 2 * 2 bytes
    const int SM0 = 64 * 104 * 4;   // 26,624
    const int SM1 = 64 * 136 * 4;   // 34,816
    const int SM2 = 64 * 264 * 4;   // 67,584
    cudaFuncSetAttribute(layer_mma<22, 32, 96,  false>,
                         cudaFuncAttributeMaxDynamicSharedMemorySize, SM0);
    cudaFuncSetAttribute(layer_mma<32, 64, 128, false>,
                         cudaFuncAttributeMaxDynamicSharedMemorySize, SM1);
    cudaFuncSetAttribute(layer_mma<64, 64, 256, true>,
                         cudaFuncAttributeMaxDynamicSharedMemorySize, SM2);

    const int EB = (N_EDGES + 255) / 256;
    const int NB = (N_NODES + 255) / 256;
    const int GB = (N_NODES + 63) / 64;            // 2561 blocks

    // ---- CSR build + weight packing (shared prep) ----
    zero_cnt<<<NB, 256>>>((const unsigned*)ei);
    convert_hist<<<EB, 256>>>(ei);
    scan1<<<SCAN_NB, SCAN_B>>>();
    scan2<<<1, 256>>>();
    scan3<<<NB, 256>>>();
    fill_gauss<<<EB, 256>>>(ea, mu[0], sg[0], mu[1], sg[1], mu[2], sg[2]);
    pack_bg<22, 32, 96 ><<<(32 * 96  + 255) / 256, 256>>>(g[0], rt[0], B0h, B0l);
    pack_bg<32, 64, 128><<<(64 * 128 + 255) / 256, 256>>>(g[1], rt[1], B1h, B1l);
    pack_bg<64, 64, 256><<<(64 * 256 + 255) / 256, 256>>>(g[2], rt[2], B2h, B2l);

    // ---- fused layers (bf16x3 HMMA, batched gather) ----
    layer_mma<22, 32, 96,  false><<<GB, 256, SM0>>>(x,  B0h, B0l, g4,                       bi[0], fcw, fcb, h0);
    layer_mma<32, 64, 128, false><<<GB, 256, SM1>>>(h0, B1h, B1l, g4 + N_EDGES,             bi[1], fcw, fcb, h1);
    layer_mma<64, 64, 256, true ><<<GB, 256, SM2>>>(h1, B2h, B2l, g4 + 2 * (size_t)N_EDGES, bi[2], fcw, fcb, out);
}